// round 14
// baseline (speedup 1.0000x reference)
#include <cuda_runtime.h>
#include <cstdint>

// Problem constants
#define BN 131072
#define DD 256
#define HH 100
#define HP 104      // H cols padded to multiple of 8 (cols 100..103 exact zeros)
#define HS 108      // H smem stride (floats)  -> conflict-free LDS.32
#define W1S 108     // W1 chunk stride (uint2) -> conflict-free LDS.64
#define W2SF 264    // W2 smem stride (floats) -> conflict-free LDS.32, 16B-aligned rows
#define NEWTON 8    // quadratic convergence from above the root; fixed point by ~iter 6

// Shared memory layout (bytes)
#define OFF_H   0                        // H: 256*108*4        = 110,592
#define OFF_U   110592                   // union: 2x W1 chunk (110,592) / W2f (109,824)
#define OFF_WT  221184                   // [HP] W1[0,:]          (416)
#define OFF_B1  221600                   // [HP] b1               (416)
#define OFF_R2  222016                   // [2][128] r2 partials (1024)
#define OFF_SC  223040                   // [128] scales          (512)
#define OFF_B2  223552                   // [DD] b2              (1024)
#define SMEM_TOTAL 224576                // < 227 KB cap

__device__ __forceinline__ uint32_t f2tf32(float x) {
    uint32_t r; asm("cvt.rna.tf32.f32 %0, %1;" : "=r"(r) : "f"(x)); return r;
}
__device__ __forceinline__ uint2 split32(float x) {
    uint2 o;
    o.x = f2tf32(x);
    o.y = f2tf32(x - __uint_as_float(o.x));
    return o;
}
// Robust tanh: ~1e-6 accuracy with or without --use_fast_math; correct +/-1 saturation.
__device__ __forceinline__ float tanh_fast(float x) {
    float e = __expf(2.0f * x);
    return 1.0f - 2.0f / (e + 1.0f);
}
__device__ __forceinline__ void mma8(float c[4], const uint32_t a[4], uint32_t b0, uint32_t b1) {
    asm volatile(
        "mma.sync.aligned.m16n8k8.row.col.f32.tf32.tf32.f32 "
        "{%0,%1,%2,%3}, {%4,%5,%6,%7}, {%8,%9}, {%0,%1,%2,%3};\n"
        : "+f"(c[0]), "+f"(c[1]), "+f"(c[2]), "+f"(c[3])
        : "r"(a[0]), "r"(a[1]), "r"(a[2]), "r"(a[3]), "r"(b0), "r"(b1));
}

// ---------------------------------------------------------------------------
// Fused kernel, 256 batch rows per block:
//   Phase 1: Hs = tanh([t,z] @ W1 + b1)   (3xTF32; W1 double-buffered K-chunks)
//   Phase 2: p = Hs @ W2 + b2 (3xTF32; W2 staged in two halves, the first
//            hidden behind the phase-1 epilogue; A fragments register-
//            prefetched one k8 ahead), r2 = ||p||^2, Lambert-W Newton
//            (MUFU-based exp), out = -scale * p (2 x 128 rows)
// ---------------------------------------------------------------------------
__global__ __launch_bounds__(256, 1) void fused_kernel(
    const float* __restrict__ z, const float* __restrict__ t,
    const float* __restrict__ W1, const float* __restrict__ b1,
    const float* __restrict__ W2, const float* __restrict__ b2,
    float* __restrict__ out)
{
    extern __shared__ unsigned char smem_raw[];
    float* Hf       = (float*)(smem_raw + OFF_H);    // [256][HS]
    uint2* W1c0     = (uint2*)(smem_raw + OFF_U);    // [64][W1S] ping (55,296 B)
    uint2* W1c1     = W1c0 + 64 * W1S;               // [64][W1S] pong
    float* W2f      = (float*)(smem_raw + OFF_U);    // [104][W2SF] (phase 2)
    float* wt_s     = (float*)(smem_raw + OFF_WT);   // [HP]
    float* b1_s     = (float*)(smem_raw + OFF_B1);   // [HP]
    float* r2buf    = (float*)(smem_raw + OFF_R2);   // [2][128]
    float* scalebuf = (float*)(smem_raw + OFF_SC);   // [128]
    float* b2_s     = (float*)(smem_raw + OFF_B2);   // [DD]

    const int tid = threadIdx.x;
    const int wid = tid >> 5, lane = tid & 31;
    const int r4 = lane >> 2, c = lane & 3;

    // ------------------------- Phase 1 -------------------------
    const int rowA = blockIdx.x * 256 + wid * 32 + r4;   // rows rowA, +8, +16, +24
    const float* p0 = z + (size_t)rowA * DD;
    const float* p1 = p0 + 8 * DD;
    const float* p2 = p0 + 16 * DD;
    const float* p3 = p0 + 24 * DD;

    // Early independent LDGs: first A fragments + the 4 t scalars + b2 stage.
    float ar0 = p0[c],     ar1 = p1[c],     ar2 = p0[c + 4], ar3 = p1[c + 4];
    float br0 = p2[c],     br1 = p3[c],     br2 = p2[c + 4], br3 = p3[c + 4];
    const float t0 = t[rowA], t1 = t[rowA + 8], t2 = t[rowA + 16], t3 = t[rowA + 24];

    b2_s[tid] = b2[tid];                 // 256 threads, 256 floats; hidden latency
    if (tid < HP) {
        wt_s[tid] = (tid < HH) ? W1[tid] : 0.0f;
        b1_s[tid] = (tid < HH) ? b1[tid] : 0.0f;
    }

    float acc0[13][4], acc1[13][4];
    #pragma unroll
    for (int i = 0; i < 13; i++) {
        acc0[i][0]=acc0[i][1]=acc0[i][2]=acc0[i][3]=0.0f;
        acc1[i][0]=acc1[i][1]=acc1[i][2]=acc1[i][3]=0.0f;
    }

    // Staging registers for one 64-K-row W1 chunk (27 elems/thread).
    float v[27];
    // Preload + store chunk 0 into ping.
    #pragma unroll
    for (int k = 0; k < 27; k++) {
        int e  = tid + k * 256;
        int kr = e / W1S;
        int n  = e - kr * W1S;
        v[k] = (n < HH) ? W1[(kr + 1) * HH + n] : 0.0f;
    }
    #pragma unroll
    for (int k = 0; k < 27; k++) W1c0[tid + k * 256] = split32(v[k]);
    __syncthreads();

    #pragma unroll 1
    for (int chunk = 0; chunk < 4; chunk++) {
        uint2* cur = (chunk & 1) ? W1c1 : W1c0;
        uint2* nxt = (chunk & 1) ? W1c0 : W1c1;

        // Issue next chunk's LDGs before the MMA burst (latency hidden).
        if (chunk < 3) {
            #pragma unroll
            for (int k = 0; k < 27; k++) {
                int e  = tid + k * 256;
                int kr = e / W1S;
                int n  = e - kr * W1S;
                v[k] = (n < HH) ? W1[((chunk + 1) * 64 + kr + 1) * HH + n] : 0.0f;
            }
        }

        #pragma unroll 1
        for (int k8l = 0; k8l < 8; k8l++) {
            int k8 = chunk * 8 + k8l;
            uint2 a0 = split32(ar0), a1 = split32(ar1), a2 = split32(ar2), a3 = split32(ar3);
            uint2 b0s = split32(br0), b1s = split32(br1), b2s = split32(br2), b3s = split32(br3);
            if (k8 < 31) {
                int kb = (k8 + 1) * 8;
                ar0 = p0[kb + c]; ar1 = p1[kb + c]; ar2 = p0[kb + c + 4]; ar3 = p1[kb + c + 4];
                br0 = p2[kb + c]; br1 = p3[kb + c]; br2 = p2[kb + c + 4]; br3 = p3[kb + c + 4];
            }
            uint32_t ah0[4] = {a0.x, a1.x, a2.x, a3.x};
            uint32_t al0[4] = {a0.y, a1.y, a2.y, a3.y};
            uint32_t ah1[4] = {b0s.x, b1s.x, b2s.x, b3s.x};
            uint32_t al1[4] = {b0s.y, b1s.y, b2s.y, b3s.y};
            const uint2* B0 = cur + (k8l * 8 + c) * W1S + r4;
            const uint2* B1 = B0 + 4 * W1S;
            #pragma unroll
            for (int nt = 0; nt < 13; nt++) {
                uint2 bb0 = B0[nt * 8];
                uint2 bb1 = B1[nt * 8];
                mma8(acc0[nt], ah0, bb0.x, bb1.x);   // hi*hi
                mma8(acc0[nt], al0, bb0.x, bb1.x);   // lo*hi
                mma8(acc0[nt], ah0, bb0.y, bb1.y);   // hi*lo
                mma8(acc1[nt], ah1, bb0.x, bb1.x);
                mma8(acc1[nt], al1, bb0.x, bb1.x);
                mma8(acc1[nt], ah1, bb0.y, bb1.y);
            }
        }

        if (chunk < 3) {
            #pragma unroll
            for (int k = 0; k < 27; k++) nxt[tid + k * 256] = split32(v[k]);
            __syncthreads();   // STS drained; all warps done reading cur
        }
    }

    // Phase-1 epilogue (split in two) + hidden W2 part-1 prefetch.
    // W2 part 1 = rows 0..51 -> W2f bytes [0, 54,880) which lie inside the
    // W1c0 region (55,296 B), dead for all warps since the end-of-chunk-2
    // barrier. Chunk 3 reads only W1c1, so these STS are race-free.
    float4 w2a[13];
    {
        float* o0 = Hf + (wid * 32 + r4) * HS;
        float* o1 = o0 + 8 * HS;
        float* o2 = o0 + 16 * HS;
        float* o3 = o0 + 24 * HS;
        #pragma unroll
        for (int nt = 0; nt < 7; nt++) {
            int n = nt * 8 + c * 2;
            float w0 = wt_s[n], w1v = wt_s[n + 1];
            float q0 = b1_s[n], q1  = b1_s[n + 1];
            *(float2*)(o0 + n) = make_float2(tanh_fast(acc0[nt][0] + t0 * w0 + q0),
                                             tanh_fast(acc0[nt][1] + t0 * w1v + q1));
            *(float2*)(o1 + n) = make_float2(tanh_fast(acc0[nt][2] + t1 * w0 + q0),
                                             tanh_fast(acc0[nt][3] + t1 * w1v + q1));
            *(float2*)(o2 + n) = make_float2(tanh_fast(acc1[nt][0] + t2 * w0 + q0),
                                             tanh_fast(acc1[nt][1] + t2 * w1v + q1));
            *(float2*)(o3 + n) = make_float2(tanh_fast(acc1[nt][2] + t3 * w0 + q0),
                                             tanh_fast(acc1[nt][3] + t3 * w1v + q1));
        }
        // Midpoint: ~half of acc is dead; issue the W2 part-1 LDG batch (MLP=13)
        // whose latency is hidden by the remaining tanh work below.
        #pragma unroll
        for (int k = 0; k < 13; k++) {
            int e = tid + k * 256;          // float4 index 0..3327 -> rows 0..51
            int r = e >> 6, q = e & 63;
            w2a[k] = *(const float4*)(W2 + r * DD + q * 4);
        }
        #pragma unroll
        for (int nt = 7; nt < 13; nt++) {
            int n = nt * 8 + c * 2;
            float w0 = wt_s[n], w1v = wt_s[n + 1];
            float q0 = b1_s[n], q1  = b1_s[n + 1];
            *(float2*)(o0 + n) = make_float2(tanh_fast(acc0[nt][0] + t0 * w0 + q0),
                                             tanh_fast(acc0[nt][1] + t0 * w1v + q1));
            *(float2*)(o1 + n) = make_float2(tanh_fast(acc0[nt][2] + t1 * w0 + q0),
                                             tanh_fast(acc0[nt][3] + t1 * w1v + q1));
            *(float2*)(o2 + n) = make_float2(tanh_fast(acc1[nt][0] + t2 * w0 + q0),
                                             tanh_fast(acc1[nt][1] + t2 * w1v + q1));
            *(float2*)(o3 + n) = make_float2(tanh_fast(acc1[nt][2] + t3 * w0 + q0),
                                             tanh_fast(acc1[nt][3] + t3 * w1v + q1));
        }
    }
    // Store W2 part 1 (into dead W1c0 region; no barrier needed before this).
    #pragma unroll
    for (int k = 0; k < 13; k++) {
        int e = tid + k * 256;
        int r = e >> 6, q = e & 63;
        *(float4*)(W2f + r * W2SF + q * 4) = w2a[k];
    }
    __syncthreads();    // H visible; all of W1c0/W1c1 dead; part-1 W2 visible

    // W2 part 2: rows 52..103 (rows >= 100 zero). Overlaps W1c1 -> must be
    // after the barrier above.
    #pragma unroll
    for (int k = 0; k < 13; k++) {
        int e = 3328 + tid + k * 256;       // float4 index -> rows 52..103
        int r = e >> 6, q = e & 63;
        w2a[k] = (r < HH) ? *(const float4*)(W2 + r * DD + q * 4)
                          : make_float4(0.f, 0.f, 0.f, 0.f);
    }
    #pragma unroll
    for (int k = 0; k < 13; k++) {
        int e = 3328 + tid + k * 256;
        int r = e >> 6, q = e & 63;
        *(float4*)(W2f + r * W2SF + q * 4) = w2a[k];
    }
    __syncthreads();

    // ------------------------- Phase 2 -------------------------
    const int rg = wid >> 1, hf_ = wid & 1;
    const int m0 = rg * 32, n0 = hf_ * 128;

    #pragma unroll 1
    for (int ph = 0; ph < 2; ph++) {
        const int rowL = ph * 128 + m0 + r4;       // block-local rows rowL, +8, +16, +24
        const float* hA0 = Hf + rowL * HS;
        const float* hA1 = hA0 + 8 * HS;
        const float* hA2 = hA0 + 16 * HS;
        const float* hA3 = hA0 + 24 * HS;

        float d0[16][4], d1[16][4];
        #pragma unroll
        for (int i = 0; i < 16; i++) {
            d0[i][0]=d0[i][1]=d0[i][2]=d0[i][3]=0.0f;
            d1[i][0]=d1[i][1]=d1[i][2]=d1[i][3]=0.0f;
        }

        // Register-prefetched A values (mirrors phase 1's pattern).
        float x0 = hA0[c],     x1 = hA1[c],     x2 = hA0[c + 4], x3 = hA1[c + 4];
        float y0 = hA2[c],     y1 = hA3[c],     y2 = hA2[c + 4], y3 = hA3[c + 4];

        #pragma unroll 1
        for (int k8 = 0; k8 < 13; k8++) {
            int kb = k8 * 8;
            uint2 a0 = split32(x0), a1 = split32(x1), a2 = split32(x2), a3 = split32(x3);
            uint2 e0 = split32(y0), e1 = split32(y1), e2 = split32(y2), e3 = split32(y3);
            if (k8 < 12) {
                int kb2 = kb + 8;
                x0 = hA0[kb2 + c]; x1 = hA1[kb2 + c]; x2 = hA0[kb2 + c + 4]; x3 = hA1[kb2 + c + 4];
                y0 = hA2[kb2 + c]; y1 = hA3[kb2 + c]; y2 = hA2[kb2 + c + 4]; y3 = hA3[kb2 + c + 4];
            }
            uint32_t ah0[4] = {a0.x, a1.x, a2.x, a3.x};
            uint32_t al0[4] = {a0.y, a1.y, a2.y, a3.y};
            uint32_t ah1[4] = {e0.x, e1.x, e2.x, e3.x};
            uint32_t al1[4] = {e0.y, e1.y, e2.y, e3.y};
            const float* Bp = W2f + (kb + c) * W2SF + n0 + r4;
            #pragma unroll
            for (int nt = 0; nt < 16; nt++) {
                uint2 s0 = split32(Bp[nt * 8]);
                uint2 s1 = split32(Bp[4 * W2SF + nt * 8]);
                mma8(d0[nt], ah0, s0.x, s1.x);
                mma8(d0[nt], al0, s0.x, s1.x);
                mma8(d0[nt], ah0, s0.y, s1.y);
                mma8(d1[nt], ah1, s0.x, s1.x);
                mma8(d1[nt], al1, s0.x, s1.x);
                mma8(d1[nt], ah1, s0.y, s1.y);
            }
        }

        // p = d + b2 ; per-lane partial ||p||^2 for the 4 rows this lane owns
        float s00 = 0.0f, s01 = 0.0f, s10 = 0.0f, s11 = 0.0f;
        #pragma unroll
        for (int nt = 0; nt < 16; nt++) {
            int n = n0 + nt * 8 + c * 2;
            float q0 = b2_s[n], q1 = b2_s[n + 1];
            d0[nt][0] += q0; d0[nt][1] += q1;
            d0[nt][2] += q0; d0[nt][3] += q1;
            d1[nt][0] += q0; d1[nt][1] += q1;
            d1[nt][2] += q0; d1[nt][3] += q1;
            s00 += d0[nt][0] * d0[nt][0] + d0[nt][1] * d0[nt][1];
            s01 += d0[nt][2] * d0[nt][2] + d0[nt][3] * d0[nt][3];
            s10 += d1[nt][0] * d1[nt][0] + d1[nt][1] * d1[nt][1];
            s11 += d1[nt][2] * d1[nt][2] + d1[nt][3] * d1[nt][3];
        }
        s00 += __shfl_xor_sync(0xffffffffu, s00, 1);
        s00 += __shfl_xor_sync(0xffffffffu, s00, 2);
        s01 += __shfl_xor_sync(0xffffffffu, s01, 1);
        s01 += __shfl_xor_sync(0xffffffffu, s01, 2);
        s10 += __shfl_xor_sync(0xffffffffu, s10, 1);
        s10 += __shfl_xor_sync(0xffffffffu, s10, 2);
        s11 += __shfl_xor_sync(0xffffffffu, s11, 1);
        s11 += __shfl_xor_sync(0xffffffffu, s11, 2);
        if (c == 0) {
            r2buf[hf_ * 128 + m0 + r4]      = s00;
            r2buf[hf_ * 128 + m0 + r4 + 8]  = s01;
            r2buf[hf_ * 128 + m0 + r4 + 16] = s10;
            r2buf[hf_ * 128 + m0 + r4 + 24] = s11;
        }
        __syncthreads();

        // One thread per row: Lambert-W Newton. The fixed point satisfies
        // w * exp~(w) = r2 for whichever exp~ is used, so __expf (MUFU) only
        // perturbs scale by ~1e-6 rel while cutting the serial chain ~5x.
        if (tid < 128) {
            float r2 = r2buf[tid] + r2buf[128 + tid];
            float w = log1pf(r2);
            #pragma unroll
            for (int i = 0; i < NEWTON; i++) {
                float ew = __expf(w);
                w = w - (w * ew - r2) / ((1.0f + w) * ew);
            }
            w = fmaxf(w, 0.0f);
            float tn = sqrtf(w);
            float r  = sqrtf(r2);
            scalebuf[tid] = (r > 1e-12f) ? (tn / fmaxf(r, 1e-12f)) : 1.0f;
        }
        __syncthreads();

        const float sa0 = -scalebuf[m0 + r4];
        const float sa1 = -scalebuf[m0 + r4 + 8];
        const float sa2 = -scalebuf[m0 + r4 + 16];
        const float sa3 = -scalebuf[m0 + r4 + 24];
        float* o0 = out + (size_t)(blockIdx.x * 256 + rowL) * DD;
        float* o1 = o0 + 8 * DD;
        float* o2 = o0 + 16 * DD;
        float* o3 = o0 + 24 * DD;
        #pragma unroll
        for (int nt = 0; nt < 16; nt++) {
            int n = n0 + nt * 8 + c * 2;
            *(float2*)(o0 + n) = make_float2(sa0 * d0[nt][0], sa0 * d0[nt][1]);
            *(float2*)(o1 + n) = make_float2(sa1 * d0[nt][2], sa1 * d0[nt][3]);
            *(float2*)(o2 + n) = make_float2(sa2 * d1[nt][0], sa2 * d1[nt][1]);
            *(float2*)(o3 + n) = make_float2(sa3 * d1[nt][2], sa3 * d1[nt][3]);
        }
    }
}

extern "C" void kernel_launch(void* const* d_in, const int* in_sizes, int n_in,
                              void* d_out, int out_size)
{
    // Bind inputs by unique element count (robust to metadata ordering):
    //   z = 131072*256, t = 131072, W1 = 257*100, b1 = 100, W2 = 100*256, b2 = 256.
    const float *z = 0, *t = 0, *W1 = 0, *b1 = 0, *W2 = 0, *b2 = 0;
    for (int i = 0; i < n_in; i++) {
        switch (in_sizes[i]) {
            case BN * DD:        z  = (const float*)d_in[i]; break;
            case BN:             t  = (const float*)d_in[i]; break;
            case (DD + 1) * HH:  W1 = (const float*)d_in[i]; break;
            case HH:             b1 = (const float*)d_in[i]; break;
            case HH * DD:        W2 = (const float*)d_in[i]; break;
            case DD:             b2 = (const float*)d_in[i]; break;
            default: break;
        }
    }
    // Fallback to positional order if any size failed to match.
    if (!z || !t || !W1 || !b1 || !W2 || !b2) {
        z  = (const float*)d_in[0];
        t  = (const float*)d_in[1];
        W1 = (const float*)d_in[2];
        b1 = (const float*)d_in[3];
        W2 = (const float*)d_in[4];
        b2 = (const float*)d_in[5];
    }
    float* out = (float*)d_out;

    cudaFuncSetAttribute(fused_kernel, cudaFuncAttributeMaxDynamicSharedMemorySize, SMEM_TOTAL);
    fused_kernel<<<BN / 256, 256, SMEM_TOTAL>>>(z, t, W1, b1, W2, b2, out);
}